// round 9
// baseline (speedup 1.0000x reference)
#include <cuda_runtime.h>
#include <cuda_bf16.h>
#include <cooperative_groups.h>

namespace cgr = cooperative_groups;

// Fixed problem shapes
#define B_  4
#define T_  16
#define O_  32
#define H_  181
#define W_  360
#define BT_ (B_ * T_)          // 64 images
#define HW_ (H_ * W_)          // 65160 px

#define GAUSS_C (-0.5f / (2.5f * 2.5f + 1e-8f))
#define EPS_    1e-8f

// Windowed tables: 48 slots, valid at slots [8..40] (33 grid indices),
// slot s <-> grid index start + s - 8. Out-of-window slots hold 0 so
// clamped reads are branchless.
#define WSLOT 48

#define NTHREADS 768           // 3 groups of 256 threads
#define CLUSTER  2             // 2 CTAs per image
#define NWARPS   (NTHREADS / 32)

// ---------------------------------------------------------------------------
// One cluster (2 CTAs) per image. Each CTA:
//   Phase 1: windowed exp tables in SMEM.
//   Phase 2: gather its 9 patches (3 row bands x 3 col patches) into
//            registers (2x8 per-thread tile), local max.
//   Max exchange via DSMEM + cluster.sync.
//   Phase 3: scale registers and store (no recompute).
// ---------------------------------------------------------------------------
__global__ __launch_bounds__(NTHREADS, 1) __cluster_dims__(CLUSTER, 1, 1)
void traj_fused_kernel(const float* __restrict__ traj,
                       const float* __restrict__ lat,
                       const float* __restrict__ lon,
                       float* __restrict__ out)
{
    __shared__ float straj[O_ * 2];
    __shared__ float slatw[O_ * WSLOT];   // 6 KB
    __shared__ float slonw[O_ * WSLOT];   // 6 KB
    __shared__ int   slats[O_];
    __shared__ int   slons[O_];
    __shared__ float sred[NWARPS];
    __shared__ float smax_own;
    __shared__ float smax_peer;

    cgr::cluster_group cluster = cgr::this_cluster();
    const unsigned rank = cluster.block_rank();     // 0 or 1
    const int img = blockIdx.x >> 1;
    const int tid = threadIdx.x;

    // ---- Phase 1: tables ----
    if (tid < O_ * 2) straj[tid] = traj[img * O_ * 2 + tid];
    __syncthreads();

    if (tid < O_) {
        const float lat_t = straj[tid * 2 + 0];
        const float lon_t = straj[tid * 2 + 1];
        // lat grid: -90 + i (step 1.0); lon grid: -180 + i*(360/359)
        slats[tid] = (int)floorf(lat_t + 90.0f) - 16;
        slons[tid] = (int)floorf((lon_t + 180.0f) * (359.0f / 360.0f)) - 16;
    }
    __syncthreads();

    for (int i = tid; i < O_ * 2 * WSLOT; i += NTHREADS) {
        const int pl = i / (2 * WSLOT);
        const int s  = i % (2 * WSLOT);
        if (s < WSLOT) {
            int gi = slats[pl] + s - 8;
            float v = 0.0f;
            if (s >= 8 && s <= 40 && gi >= 0 && gi < H_) {
                float d = lat[gi] - straj[pl * 2 + 0];
                v = __expf(GAUSS_C * d * d);
            }
            slatw[pl * WSLOT + s] = v;
        } else {
            int t  = s - WSLOT;
            int gi = slons[pl] + t - 8;
            float v = 0.0f;
            if (t >= 8 && t <= 40 && gi >= 0 && gi < W_) {
                float d = lon[gi] - straj[pl * 2 + 1];
                v = __expf(GAUSS_C * d * d);
            }
            slonw[pl * WSLOT + t] = v;
        }
    }
    __syncthreads();

    // ---- Geometry: 256-thread group owns row band (rank*3+g), 3 col patches ----
    // Group: 8 warps as 4 (rows) x 2 (cols); warp patch 8 rows x 64 cols.
    // Lane: rg = l>>3 (row pair), cg = l&7 (8-col group). Thread tile 2x8.
    const int g    = tid >> 8;            // 0..2
    const int gtid = tid & 255;
    const int w    = gtid >> 5, l = gtid & 31;
    const int wr   = w >> 1,  wc = w & 1;
    const int rg   = l >> 3,  cgi = l & 7;
    const int rOff = wr * 8 + rg * 2;
    const int cOff = wc * 64 + cgi * 8;

    const int BR0 = ((int)rank * 3 + g) * 32;
    const int R0  = BR0 + rOff;
    const int tls = slats[l], tcs = slons[l];   // this lane's test point

    // ---- Phase 2: gather into registers + local max ----
    float acc[3][2][8];
    #pragma unroll
    for (int pc = 0; pc < 3; pc++)
        #pragma unroll
        for (int j = 0; j < 2; j++)
            #pragma unroll
            for (int k = 0; k < 8; k++) acc[pc][j][k] = 0.0f;

    float lmax = 0.0f;
    #pragma unroll
    for (int pc = 0; pc < 3; pc++) {
        const int BC0 = pc * 128;
        const int C0  = BC0 + cOff;

        const bool act = !(BR0 + 31 < tls || BR0 > tls + 32 ||
                           BC0 + 127 < tcs || BC0 > tcs + 32);
        unsigned mask = __ballot_sync(0xFFFFFFFFu, act);

        for (; mask; mask &= (mask - 1)) {
            const int o = __ffs(mask) - 1;
            const int ls = slats[o], cs = slons[o];
            if (R0 + 1 < ls || R0 > ls + 32 || C0 + 7 < cs || C0 > cs + 32)
                continue;
            float a[2], v[8];
            #pragma unroll
            for (int j = 0; j < 2; j++) {
                int idx = min(max(R0 + j - ls + 8, 0), WSLOT - 1);
                a[j] = slatw[o * WSLOT + idx];
            }
            #pragma unroll
            for (int k = 0; k < 8; k++) {
                int idx = min(max(C0 + k - cs + 8, 0), WSLOT - 1);
                v[k] = slonw[o * WSLOT + idx];
            }
            #pragma unroll
            for (int j = 0; j < 2; j++)
                #pragma unroll
                for (int k = 0; k < 8; k++)
                    acc[pc][j][k] = fmaf(a[j], v[k], acc[pc][j][k]);
        }

        const bool colok = (C0 < W_);     // tile is 8-aligned; W_ % 8 == 0
        #pragma unroll
        for (int j = 0; j < 2; j++) {
            if (colok && (R0 + j) < H_) {
                #pragma unroll
                for (int k = 0; k < 8; k++)
                    lmax = fmaxf(lmax, acc[pc][j][k]);
            }
        }
    }

    // ---- Block max reduce, then cross-CTA exchange via DSMEM ----
    #pragma unroll
    for (int off = 16; off > 0; off >>= 1)
        lmax = fmaxf(lmax, __shfl_xor_sync(0xFFFFFFFFu, lmax, off));
    if (l == 0) sred[tid >> 5] = lmax;
    __syncthreads();
    if (tid == 0) {
        float bmax = 0.0f;
        #pragma unroll
        for (int i = 0; i < NWARPS; i++) bmax = fmaxf(bmax, sred[i]);
        smax_own = bmax;
        float* peer = (float*)cluster.map_shared_rank(&smax_peer, rank ^ 1u);
        *peer = bmax;
    }
    cluster.sync();
    const float inv = 1.0f / (fmaxf(smax_own, smax_peer) + EPS_);

    // ---- Phase 3: scale registers and store ----
    float* oimg = out + img * HW_;
    #pragma unroll
    for (int pc = 0; pc < 3; pc++) {
        const int C0 = pc * 128 + cOff;
        const bool colok = (C0 < W_);
        #pragma unroll
        for (int j = 0; j < 2; j++) {
            const int r = R0 + j;
            if (colok && r < H_) {
                float4 v0 = make_float4(acc[pc][j][0] * inv, acc[pc][j][1] * inv,
                                        acc[pc][j][2] * inv, acc[pc][j][3] * inv);
                float4 v1 = make_float4(acc[pc][j][4] * inv, acc[pc][j][5] * inv,
                                        acc[pc][j][6] * inv, acc[pc][j][7] * inv);
                *reinterpret_cast<float4*>(&oimg[r * W_ + C0])     = v0;
                *reinterpret_cast<float4*>(&oimg[r * W_ + C0 + 4]) = v1;
            }
        }
    }
}

// ---------------------------------------------------------------------------
extern "C" void kernel_launch(void* const* d_in, const int* in_sizes, int n_in,
                              void* d_out, int out_size)
{
    const float* traj = (const float*)d_in[0];  // (4,16,32,2)
    const float* lat  = (const float*)d_in[1];  // (181,)
    const float* lon  = (const float*)d_in[2];  // (360,)
    float* out = (float*)d_out;                 // (64,181,360) f32

    traj_fused_kernel<<<BT_ * CLUSTER, NTHREADS>>>(traj, lat, lon, out);
}

// round 12
// speedup vs baseline: 1.1213x; 1.1213x over previous
#include <cuda_runtime.h>
#include <cuda_bf16.h>
#include <cooperative_groups.h>

namespace cgr = cooperative_groups;

// Fixed problem shapes
#define B_  4
#define T_  16
#define O_  32
#define H_  181
#define W_  360
#define BT_ (B_ * T_)          // 64 images
#define HW_ (H_ * W_)          // 65160 px

#define GAUSS_C (-0.5f / (2.5f * 2.5f + 1e-8f))
#define EPS_    1e-8f

// Windowed tables: 48 slots, valid at slots [8..40] (33 grid indices),
// slot s <-> grid index start + s - 8. Out-of-window slots hold 0, so a
// single unsigned clamp min((unsigned)x, 47) yields 0 for any out-of-window
// offset (negative wraps to huge -> 47; >47 -> 47; slot 47 == 0).
#define WSLOT 48

#define NTHREADS 768           // 3 groups of 256 threads
#define CLUSTER  2             // 2 CTAs per image
#define NWARPS   (NTHREADS / 32)

// ---------------------------------------------------------------------------
// One cluster (2 CTAs) per image.
//   Phase 1: windowed exp tables in SMEM.
//   Phase 2: gather 9 patches (3 row bands x 3 col patches per CTA) into
//            registers. Warp-granular ballot: each warp tests points against
//            its OWN 16x32 footprint (not the 32x128 block patch).
//   Max exchange via DSMEM + cluster.sync.
//   Phase 3: scale registers and store (no recompute).
// ---------------------------------------------------------------------------
__global__ __launch_bounds__(NTHREADS, 1) __cluster_dims__(CLUSTER, 1, 1)
void traj_fused_kernel(const float* __restrict__ traj,
                       const float* __restrict__ lat,
                       const float* __restrict__ lon,
                       float* __restrict__ out)
{
    __shared__ float straj[O_ * 2];
    __shared__ float slatw[O_ * WSLOT];   // 6 KB
    __shared__ float slonw[O_ * WSLOT];   // 6 KB
    __shared__ int   slats[O_];
    __shared__ int   slons[O_];
    __shared__ float sred[NWARPS];
    __shared__ float smax_own;
    __shared__ float smax_peer;

    cgr::cluster_group cluster = cgr::this_cluster();
    const unsigned rank = cluster.block_rank();     // 0 or 1
    const int img = blockIdx.x >> 1;
    const int tid = threadIdx.x;

    // ---- Phase 1: tables (one barrier between straj load and use) ----
    if (tid < O_ * 2) straj[tid] = traj[img * O_ * 2 + tid];
    __syncthreads();

    if (tid < O_) {
        // lat grid: -90 + i (step 1.0); lon grid: -180 + i*(360/359)
        slats[tid] = (int)floorf(straj[tid * 2 + 0] + 90.0f) - 16;
        slons[tid] = (int)floorf((straj[tid * 2 + 1] + 180.0f) * (359.0f / 360.0f)) - 16;
    }

    for (int i = tid; i < O_ * 2 * WSLOT; i += NTHREADS) {
        const int pl = i / (2 * WSLOT);
        const int s  = i % (2 * WSLOT);
        if (s < WSLOT) {
            const float lat_t = straj[pl * 2 + 0];
            const int start = (int)floorf(lat_t + 90.0f) - 16;
            const int gi = start + s - 8;
            float v = 0.0f;
            if (s >= 8 && s <= 40 && gi >= 0 && gi < H_) {
                float d = lat[gi] - lat_t;
                v = __expf(GAUSS_C * d * d);
            }
            slatw[pl * WSLOT + s] = v;
        } else {
            const float lon_t = straj[pl * 2 + 1];
            const int start = (int)floorf((lon_t + 180.0f) * (359.0f / 360.0f)) - 16;
            const int t  = s - WSLOT;
            const int gi = start + t - 8;
            float v = 0.0f;
            if (t >= 8 && t <= 40 && gi >= 0 && gi < W_) {
                float d = lon[gi] - lon_t;
                v = __expf(GAUSS_C * d * d);
            }
            slonw[pl * WSLOT + t] = v;
        }
    }
    __syncthreads();

    // ---- Geometry: 256-thr group owns row band (rank*3+g), 3 col patches.
    // Group = 2x4 warps; warp footprint 16 rows x 32 cols; thread tile 2x8.
    const int g    = tid >> 8;            // 0..2
    const int gtid = tid & 255;
    const int w    = gtid >> 5, l = gtid & 31;
    const int wr   = w >> 2,  wc = w & 3;     // warp grid 2 x 4
    const int rg   = l >> 2,  cgi = l & 3;    // lane grid 8 x 4
    const int rOff = wr * 16 + rg * 2;
    const int cOff = wc * 32 + cgi * 8;

    const int BR0 = ((int)rank * 3 + g) * 32;
    const int R0  = BR0 + rOff;
    const int WR0 = BR0 + wr * 16;            // warp footprint origin (rows)
    const int tls = slats[l], tcs = slons[l]; // this lane's test point

    // ---- Phase 2: gather into registers + local max ----
    float acc[3][2][8];
    #pragma unroll
    for (int pc = 0; pc < 3; pc++)
        #pragma unroll
        for (int j = 0; j < 2; j++)
            #pragma unroll
            for (int k = 0; k < 8; k++) acc[pc][j][k] = 0.0f;

    float lmax = 0.0f;
    #pragma unroll
    for (int pc = 0; pc < 3; pc++) {
        const int BC0 = pc * 128;
        const int C0  = BC0 + cOff;
        const int WC0 = BC0 + wc * 32;        // warp footprint origin (cols)

        // Warp-granular mask: only points whose 33x33 window intersects THIS
        // warp's 16x32 footprint.
        const bool act = !(WR0 + 15 < tls || WR0 > tls + 32 ||
                           WC0 + 31 < tcs || WC0 > tcs + 32);
        unsigned mask = __ballot_sync(0xFFFFFFFFu, act);

        for (; mask; mask &= (mask - 1)) {
            const int o = __ffs(mask) - 1;
            const int ls = slats[o], cs = slons[o];
            // Per-thread tile test (2 rows x 8 cols)
            if (R0 + 1 < ls || R0 > ls + 32 || C0 + 7 < cs || C0 > cs + 32)
                continue;
            const int lbase = R0 + 8 - ls;
            const int cbase = C0 + 8 - cs;
            const float* lrow = &slatw[o * WSLOT];
            const float* crow = &slonw[o * WSLOT];
            float a[2], v[8];
            #pragma unroll
            for (int j = 0; j < 2; j++)
                a[j] = lrow[min((unsigned)(lbase + j), 47u)];
            #pragma unroll
            for (int k = 0; k < 8; k++)
                v[k] = crow[min((unsigned)(cbase + k), 47u)];
            #pragma unroll
            for (int j = 0; j < 2; j++)
                #pragma unroll
                for (int k = 0; k < 8; k++)
                    acc[pc][j][k] = fmaf(a[j], v[k], acc[pc][j][k]);
        }

        const bool colok = (C0 < W_);     // tile 8-aligned; W_ % 8 == 0
        #pragma unroll
        for (int j = 0; j < 2; j++) {
            if (colok && (R0 + j) < H_) {
                #pragma unroll
                for (int k = 0; k < 8; k++)
                    lmax = fmaxf(lmax, acc[pc][j][k]);
            }
        }
    }

    // ---- Block max reduce, then cross-CTA exchange via DSMEM ----
    #pragma unroll
    for (int off = 16; off > 0; off >>= 1)
        lmax = fmaxf(lmax, __shfl_xor_sync(0xFFFFFFFFu, lmax, off));
    if (l == 0) sred[tid >> 5] = lmax;
    __syncthreads();
    if (tid == 0) {
        float bmax = 0.0f;
        #pragma unroll
        for (int i = 0; i < NWARPS; i++) bmax = fmaxf(bmax, sred[i]);
        smax_own = bmax;
        float* peer = (float*)cluster.map_shared_rank(&smax_peer, rank ^ 1u);
        *peer = bmax;
    }
    cluster.sync();
    const float inv = 1.0f / (fmaxf(smax_own, smax_peer) + EPS_);

    // ---- Phase 3: scale registers and store ----
    float* oimg = out + img * HW_;
    #pragma unroll
    for (int pc = 0; pc < 3; pc++) {
        const int C0 = pc * 128 + cOff;
        const bool colok = (C0 < W_);
        #pragma unroll
        for (int j = 0; j < 2; j++) {
            const int r = R0 + j;
            if (colok && r < H_) {
                float4 v0 = make_float4(acc[pc][j][0] * inv, acc[pc][j][1] * inv,
                                        acc[pc][j][2] * inv, acc[pc][j][3] * inv);
                float4 v1 = make_float4(acc[pc][j][4] * inv, acc[pc][j][5] * inv,
                                        acc[pc][j][6] * inv, acc[pc][j][7] * inv);
                *reinterpret_cast<float4*>(&oimg[r * W_ + C0])     = v0;
                *reinterpret_cast<float4*>(&oimg[r * W_ + C0 + 4]) = v1;
            }
        }
    }
}

// ---------------------------------------------------------------------------
extern "C" void kernel_launch(void* const* d_in, const int* in_sizes, int n_in,
                              void* d_out, int out_size)
{
    const float* traj = (const float*)d_in[0];  // (4,16,32,2)
    const float* lat  = (const float*)d_in[1];  // (181,)
    const float* lon  = (const float*)d_in[2];  // (360,)
    float* out = (float*)d_out;                 // (64,181,360) f32

    traj_fused_kernel<<<BT_ * CLUSTER, NTHREADS>>>(traj, lat, lon, out);
}

// round 16
// speedup vs baseline: 1.1382x; 1.0151x over previous
#include <cuda_runtime.h>
#include <cuda_bf16.h>
#include <cooperative_groups.h>

namespace cgr = cooperative_groups;

// Fixed problem shapes
#define B_  4
#define T_  16
#define O_  32
#define H_  181
#define W_  360
#define BT_ (B_ * T_)          // 64 images
#define HW_ (H_ * W_)          // 65160 px

#define GAUSS_C (-0.5f / (2.5f * 2.5f + 1e-8f))
#define EPS_    1e-8f

// Windowed tables: 48 slots, valid at slots [8..40] (33 grid indices),
// slot s <-> grid index start + s - 8. Out-of-window slots hold 0, so a
// single unsigned clamp min((unsigned)x, 47) yields 0 for any out-of-window
// offset (negative wraps huge -> 47; >47 -> 47; slot 47 == 0).
#define WSLOT 48

#define NTHREADS 768           // 3 groups of 256 threads
#define CLUSTER  2             // 2 CTAs per image
#define NWARPS   (NTHREADS / 32)

// ---------------------------------------------------------------------------
// One cluster (2 CTAs) per image.
//   Phase 0: stage lat/lon grids + traj points into SMEM (overlapped LDGs).
//   Phase 1: windowed exp tables, static thread->slot mapping, STS.128.
//   Phase 2: gather 9 patches into registers; warp-footprint ballots.
//   Max: shfl reduce -> warp0 reduce -> DSMEM exchange -> cluster.sync.
//   Phase 3: scale registers and store.
// ---------------------------------------------------------------------------
__global__ __launch_bounds__(NTHREADS, 1) __cluster_dims__(CLUSTER, 1, 1)
void traj_fused_kernel(const float* __restrict__ traj,
                       const float* __restrict__ lat,
                       const float* __restrict__ lon,
                       float* __restrict__ out)
{
    // 16B alignment is REQUIRED: phase 1 stores float4 into slatw/slonw.
    __shared__ __align__(16) float slatw[O_ * WSLOT];   // 6 KB
    __shared__ __align__(16) float slonw[O_ * WSLOT];   // 6 KB
    __shared__ __align__(16) float sgrid[H_ + W_ + 3];  // lat[0..180], lon at H_
    __shared__ __align__(16) float straj[O_ * 2];
    __shared__ int   slats[O_];
    __shared__ int   slons[O_];
    __shared__ float sred[NWARPS];
    __shared__ float smax_own;
    __shared__ float smax_peer;

    cgr::cluster_group cluster = cgr::this_cluster();
    const unsigned rank = cluster.block_rank();     // 0 or 1
    const int img = blockIdx.x >> 1;
    const int tid = threadIdx.x;

    // ---- Phase 0: overlapped staging (single LDG round) ----
    if (tid < O_ * 2) straj[tid] = traj[img * O_ * 2 + tid];
    if (tid < H_ + W_) sgrid[tid] = (tid < H_) ? lat[tid] : lon[tid - H_];
    __syncthreads();

    // ---- Phase 1: tables. Thread t: point t/24, slots (t%24)*4 .. +3.
    // 4 consecutive slots never straddle the 48-slot lat/lon boundary
    // (48 % 4 == 0). 768 threads = 32 points x 24 quads: exact cover.
    {
        const int pl = tid / 24;
        const int s0 = (tid % 24) * 4;
        const bool is_lat = (s0 < WSLOT);
        const float coord = straj[pl * 2 + (is_lat ? 0 : 1)];
        const int start = is_lat
            ? (int)floorf(coord + 90.0f) - 16
            : (int)floorf((coord + 180.0f) * (359.0f / 360.0f)) - 16;
        const int t0   = is_lat ? s0 : s0 - WSLOT;
        const int gmax = is_lat ? H_ : W_;
        const int goff = is_lat ? 0 : H_;

        if (tid < O_) {
            slats[tid] = (int)floorf(straj[tid * 2 + 0] + 90.0f) - 16;
            slons[tid] = (int)floorf((straj[tid * 2 + 1] + 180.0f) * (359.0f / 360.0f)) - 16;
        }

        float4 vv;
        float* v = &vv.x;
        #pragma unroll
        for (int j = 0; j < 4; j++) {
            const int s  = t0 + j;
            const int gi = start + s - 8;
            const bool ok = (s >= 8) & (s <= 40) & (gi >= 0) & (gi < gmax);
            const float gc = sgrid[goff + min(max(gi, 0), gmax - 1)];
            const float d  = gc - coord;
            v[j] = ok ? __expf(GAUSS_C * d * d) : 0.0f;
        }
        float* dst = is_lat ? &slatw[pl * WSLOT + t0] : &slonw[pl * WSLOT + t0];
        *reinterpret_cast<float4*>(dst) = vv;
    }
    __syncthreads();

    // ---- Geometry: 256-thr group owns row band (rank*3+g), 3 col patches.
    // Group = 2x4 warps; warp footprint 16 rows x 32 cols; thread tile 2x8.
    const int g    = tid >> 8;            // 0..2
    const int gtid = tid & 255;
    const int w    = gtid >> 5, l = gtid & 31;
    const int wr   = w >> 2,  wc = w & 3;     // warp grid 2 x 4
    const int rg   = l >> 2,  cgi = l & 3;    // lane grid 8 x 4
    const int rOff = wr * 16 + rg * 2;
    const int cOff = wc * 32 + cgi * 8;

    const int BR0 = ((int)rank * 3 + g) * 32;
    const int R0  = BR0 + rOff;
    const int WR0 = BR0 + wr * 16;            // warp footprint origin (rows)
    const int tls = slats[l], tcs = slons[l]; // this lane's test point

    // Row half of the warp-footprint test is patch-invariant.
    const bool rowok = !(WR0 + 15 < tls || WR0 > tls + 32);

    // ---- Phase 2: gather into registers + local max ----
    float acc[3][2][8];
    #pragma unroll
    for (int pc = 0; pc < 3; pc++)
        #pragma unroll
        for (int j = 0; j < 2; j++)
            #pragma unroll
            for (int k = 0; k < 8; k++) acc[pc][j][k] = 0.0f;

    float lmax = 0.0f;
    #pragma unroll
    for (int pc = 0; pc < 3; pc++) {
        const int BC0 = pc * 128;
        const int C0  = BC0 + cOff;
        const int WC0 = BC0 + wc * 32;        // warp footprint origin (cols)

        const bool act = rowok && !(WC0 + 31 < tcs || WC0 > tcs + 32);
        unsigned mask = __ballot_sync(0xFFFFFFFFu, act);

        for (; mask; mask &= (mask - 1)) {
            const int o = __ffs(mask) - 1;
            const int ls = slats[o], cs = slons[o];
            if (R0 + 1 < ls || R0 > ls + 32 || C0 + 7 < cs || C0 > cs + 32)
                continue;
            const int lbase = R0 + 8 - ls;
            const int cbase = C0 + 8 - cs;
            const float* lrow = &slatw[o * WSLOT];
            const float* crow = &slonw[o * WSLOT];
            float a[2], v[8];
            #pragma unroll
            for (int j = 0; j < 2; j++)
                a[j] = lrow[min((unsigned)(lbase + j), 47u)];
            #pragma unroll
            for (int k = 0; k < 8; k++)
                v[k] = crow[min((unsigned)(cbase + k), 47u)];
            #pragma unroll
            for (int j = 0; j < 2; j++)
                #pragma unroll
                for (int k = 0; k < 8; k++)
                    acc[pc][j][k] = fmaf(a[j], v[k], acc[pc][j][k]);
        }

        const bool colok = (C0 < W_);     // tile 8-aligned; W_ % 8 == 0
        #pragma unroll
        for (int j = 0; j < 2; j++) {
            if (colok && (R0 + j) < H_) {
                #pragma unroll
                for (int k = 0; k < 8; k++)
                    lmax = fmaxf(lmax, acc[pc][j][k]);
            }
        }
    }

    // ---- Max reduce: warp shfl -> warp0 shfl -> DSMEM exchange ----
    #pragma unroll
    for (int off = 16; off > 0; off >>= 1)
        lmax = fmaxf(lmax, __shfl_xor_sync(0xFFFFFFFFu, lmax, off));
    if (l == 0) sred[tid >> 5] = lmax;
    __syncthreads();
    if (tid < 32) {
        float v = (tid < NWARPS) ? sred[tid] : 0.0f;
        #pragma unroll
        for (int off = 16; off > 0; off >>= 1)
            v = fmaxf(v, __shfl_xor_sync(0xFFFFFFFFu, v, off));
        if (tid == 0) {
            smax_own = v;
            float* peer = (float*)cluster.map_shared_rank(&smax_peer, rank ^ 1u);
            *peer = v;
        }
    }
    cluster.sync();
    const float inv = 1.0f / (fmaxf(smax_own, smax_peer) + EPS_);

    // ---- Phase 3: scale registers and store ----
    float* oimg = out + img * HW_;
    #pragma unroll
    for (int pc = 0; pc < 3; pc++) {
        const int C0 = pc * 128 + cOff;
        const bool colok = (C0 < W_);
        #pragma unroll
        for (int j = 0; j < 2; j++) {
            const int r = R0 + j;
            if (colok && r < H_) {
                float4 v0 = make_float4(acc[pc][j][0] * inv, acc[pc][j][1] * inv,
                                        acc[pc][j][2] * inv, acc[pc][j][3] * inv);
                float4 v1 = make_float4(acc[pc][j][4] * inv, acc[pc][j][5] * inv,
                                        acc[pc][j][6] * inv, acc[pc][j][7] * inv);
                *reinterpret_cast<float4*>(&oimg[r * W_ + C0])     = v0;
                *reinterpret_cast<float4*>(&oimg[r * W_ + C0 + 4]) = v1;
            }
        }
    }
}

// ---------------------------------------------------------------------------
extern "C" void kernel_launch(void* const* d_in, const int* in_sizes, int n_in,
                              void* d_out, int out_size)
{
    const float* traj = (const float*)d_in[0];  // (4,16,32,2)
    const float* lat  = (const float*)d_in[1];  // (181,)
    const float* lon  = (const float*)d_in[2];  // (360,)
    float* out = (float*)d_out;                 // (64,181,360) f32

    traj_fused_kernel<<<BT_ * CLUSTER, NTHREADS>>>(traj, lat, lon, out);
}